// round 13
// baseline (speedup 1.0000x reference)
#include <cuda_runtime.h>
#include <cuda_fp16.h>
#include <cstdint>

#define EMBED 8192
#define U0 1024
#define KH 1040
#define U1 256
#define NHEAD 6
#define BATCH 8192

__device__ __align__(16) __half g_Wt[(size_t)U0 * EMBED];
__device__ __align__(16) __half g_hh[(size_t)BATCH * KH];
__device__ __align__(16) __half g_W1t[(size_t)NHEAD * U1 * KH];
__device__ int g_idx[BATCH];
__device__ int g_cnt[NHEAD];
__device__ int g_off[NHEAD];

__device__ __forceinline__ uint32_t smem_u32(const void* p) {
    uint32_t a;
    asm("{ .reg .u64 t; cvta.to.shared.u64 t, %1; cvt.u32.u64 %0, t; }" : "=r"(a) : "l"(p));
    return a;
}
__device__ __forceinline__ uint32_t packh2(float a, float b) {
    __half2 h = __floats2half2_rn(a, b);
    return *reinterpret_cast<uint32_t*>(&h);
}

#define CP_ASYNC16(dst, src) \
    asm volatile("cp.async.cg.shared.global [%0], [%1], 16;" ::"r"(dst), "l"(src))
#define CP_COMMIT() asm volatile("cp.async.commit_group;" ::: "memory")
#define CP_WAIT2()  asm volatile("cp.async.wait_group 2;" ::: "memory")
#define CP_WAIT1()  asm volatile("cp.async.wait_group 1;" ::: "memory")

#define LDMX4(r0, r1, r2, r3, a) \
    asm volatile("ldmatrix.sync.aligned.m8n8.x4.shared.b16 {%0,%1,%2,%3}, [%4];" \
        : "=r"(r0), "=r"(r1), "=r"(r2), "=r"(r3) : "r"(a))

#define STS128(addr, r0, r1, r2, r3) \
    asm volatile("st.shared.v4.b32 [%0], {%1,%2,%3,%4};" ::"r"(addr), "r"(r0), "r"(r1), "r"(r2), "r"(r3) : "memory")

#define MMA16816(c, a, b0, b1)                                                   \
    asm volatile("mma.sync.aligned.m16n8k16.row.col.f32.f16.f16.f32 "            \
        "{%0,%1,%2,%3}, {%4,%5,%6,%7}, {%8,%9}, {%0,%1,%2,%3};"                  \
        : "+f"((c)[0]), "+f"((c)[1]), "+f"((c)[2]), "+f"((c)[3])                 \
        : "r"((a)[0]), "r"((a)[1]), "r"((a)[2]), "r"((a)[3]), "r"(b0), "r"(b1))

// ============ K2: transpose fc_W [K][N] fp32 -> g_Wt [N][K] fp16 ============
__global__ void convert_w_kernel(const float* __restrict__ W) {
    __shared__ float tile[32][33];
    const int bx = blockIdx.x, by = blockIdx.y;
    const int tx = threadIdx.x, ty = threadIdx.y;
#pragma unroll
    for (int r = 0; r < 4; r++)
        tile[ty + r * 8][tx] = W[(size_t)(by * 32 + ty + r * 8) * U0 + bx * 32 + tx];
    __syncthreads();
#pragma unroll
    for (int r = 0; r < 4; r++) {
        int n = bx * 32 + ty + r * 8, k = by * 32 + tx;
        g_Wt[(size_t)n * EMBED + k] = __float2half_rn(tile[tx][ty + r * 8]);
    }
}

// ============ K2b: W1 [h][k(1027)][n(256)] -> g_W1t [h][n][k(1040 pad)] fp16 ============
__global__ void convert_w1_kernel(const float* __restrict__ W1) {
    __shared__ float tile[32][33];
    const int kt = blockIdx.x, nt = blockIdx.y, hd = blockIdx.z;
    const int tx = threadIdx.x, ty = threadIdx.y;
    const float* Wh = W1 + (size_t)hd * 1027 * 256;
#pragma unroll
    for (int r = 0; r < 4; r++) {
        int k = kt * 32 + ty + r * 8, n = nt * 32 + tx;
        tile[ty + r * 8][tx] = (k < 1027) ? Wh[(size_t)k * 256 + n] : 0.f;
    }
    __syncthreads();
#pragma unroll
    for (int r = 0; r < 4; r++) {
        int n = nt * 32 + ty + r * 8, k = kt * 32 + tx;
        if (k < KH)
            g_W1t[(size_t)hd * U1 * KH + (size_t)n * KH + k] = __float2half_rn(tile[tx][ty + r * 8]);
    }
}

// ============ K3: ego columns + zero pad of g_hh cols [1024,1040) fp16 ============
__global__ void ego_kernel(const float* __restrict__ ego) {
    int i = blockIdx.x * 256 + threadIdx.x;
    if (i >= BATCH * 16) return;
    int b = i >> 4, j = i & 15;
    g_hh[(size_t)b * KH + U0 + j] = __float2half_rn((j < 3) ? ego[b * 3 + j] : 0.f);
}

// ============ K4: bin rows by command (1 block, 1024 thr) ============
__global__ void prep_kernel(const int* __restrict__ cmd) {
    __shared__ int scnt[NHEAD], scur[NHEAD];
    const int tid = threadIdx.x;
    if (tid < NHEAD) scnt[tid] = 0;
    __syncthreads();
    for (int b = tid; b < BATCH; b += 1024) {
        int c = cmd[b];
        unsigned m = __match_any_sync(0xFFFFFFFFu, c);
        if ((tid & 31) == __ffs(m) - 1) atomicAdd(&scnt[c], __popc(m));
    }
    __syncthreads();
    if (tid == 0) {
        int run = 0;
        for (int g = 0; g < NHEAD; g++) { g_off[g] = run; g_cnt[g] = scnt[g]; scur[g] = run; run += scnt[g]; }
    }
    __syncthreads();
    for (int b = tid; b < BATCH; b += 1024) {
        int c = cmd[b];
        unsigned m = __match_any_sync(0xFFFFFFFFu, c);
        int leader = __ffs(m) - 1, base = 0;
        if ((tid & 31) == leader) base = atomicAdd(&scur[c], __popc(m));
        base = __shfl_sync(m, base, leader);
        g_idx[base + __popc(m & ((1u << (tid & 31)) - 1u))] = b;
    }
}

// ============ K5: GEMM1 h = relu(x @ fc_W + b) -> g_hh fp16, mma.sync ============
// A path: LDG fp32 (3 stages ahead) -> cvt fp16 -> STS (fused convert).
// W path: cp.async, one commit group per stage.
#define STG_BYTES 16384
#define NSTAGE 4
#define NITER 256

__global__ void __launch_bounds__(512) gemm1_kernel(const float* __restrict__ x,
                                                    const float* __restrict__ fcb) {
    extern __shared__ char smem[];
    const uint32_t sb = smem_u32(smem);
    const int tid = threadIdx.x;
    const int wid = tid >> 5, lane = tid & 31;
    const int wm = wid & 3, wn = wid >> 2;
    const int m0 = blockIdx.y * 128, n0 = blockIdx.x * 128;

    const __half* wt = g_Wt + (size_t)n0 * EMBED;

    const int lr = tid >> 2, lc = tid & 3;
    const uint32_t lsw0 = (uint32_t)(lr * 64 + ((lc ^ ((lr >> 1) & 3)) << 4));
    // per-thread fp32 source row: x[(m0+lr)*EMBED + k0 + lc*8 ..+8)
    const float* xrow = x + (size_t)(m0 + lr) * EMBED + lc * 8;

#define A_STS(stg, f0, f1) do {                                                   \
    uint32_t p0_ = packh2((f0).x, (f0).y), p1_ = packh2((f0).z, (f0).w);          \
    uint32_t p2_ = packh2((f1).x, (f1).y), p3_ = packh2((f1).z, (f1).w);          \
    STS128(sb + (stg) * STG_BYTES + lsw0, p0_, p1_, p2_, p3_);                    \
} while (0)

    // prologue: stages 0..2
#pragma unroll
    for (int s = 0; s < 3; s++) {
        const float4 f0 = *reinterpret_cast<const float4*>(xrow + s * 32);
        const float4 f1 = *reinterpret_cast<const float4*>(xrow + s * 32 + 4);
        A_STS(s, f0, f1);
        CP_ASYNC16(sb + s * STG_BYTES + 8192 + lsw0, wt + (size_t)lr * EMBED + s * 32 + lc * 8);
        CP_COMMIT();
    }

    float acc[2][4][4];
#pragma unroll
    for (int f = 0; f < 2; f++)
#pragma unroll
        for (int n = 0; n < 4; n++)
#pragma unroll
            for (int j = 0; j < 4; j++) acc[f][n][j] = 0.f;

    const int trow = (lane & 7) + ((lane >> 3) & 1) * 8;
    const int tkc = lane >> 4;

    for (int it = 0; it < NITER; it++) {
        const int pf = it + 3;
        float4 fa0, fa1;
        if (pf < NITER) {
            fa0 = *reinterpret_cast<const float4*>(xrow + pf * 32);
            fa1 = *reinterpret_cast<const float4*>(xrow + pf * 32 + 4);
        }
        CP_WAIT2();
        __syncthreads();
        if (pf < NITER)
            CP_ASYNC16(sb + (pf & 3) * STG_BYTES + 8192 + lsw0,
                       wt + (size_t)lr * EMBED + pf * 32 + lc * 8);
        CP_COMMIT();

        const uint32_t sA = sb + (it & 3) * STG_BYTES;
#pragma unroll
        for (int ks = 0; ks < 2; ks++) {
            uint32_t ah[2][4];
            uint32_t bf[4][2];
            const int kc = ks * 2 + tkc;
#pragma unroll
            for (int f = 0; f < 2; f++) {
                int row = wm * 32 + f * 16 + trow;
                uint32_t ad = sA + row * 64 + ((kc ^ ((row >> 1) & 3)) << 4);
                LDMX4(ah[f][0], ah[f][1], ah[f][2], ah[f][3], ad);
            }
#pragma unroll
            for (int p = 0; p < 2; p++) {
                int row = wn * 32 + p * 16 + trow;
                uint32_t bd = sA + 8192 + row * 64 + ((kc ^ ((row >> 1) & 3)) << 4);
                uint32_t r0, r1, r2, r3;
                LDMX4(r0, r1, r2, r3, bd);
                bf[2 * p][0] = r0; bf[2 * p][1] = r2;
                bf[2 * p + 1][0] = r1; bf[2 * p + 1][1] = r3;
            }
#pragma unroll
            for (int f = 0; f < 2; f++)
#pragma unroll
                for (int n = 0; n < 4; n++)
                    MMA16816(acc[f][n], ah[f], bf[n][0], bf[n][1]);
        }
        if (pf < NITER) A_STS(pf & 3, fa0, fa1);
    }

    const int qr = lane >> 2, qc = (lane & 3) << 1;
#pragma unroll
    for (int f = 0; f < 2; f++) {
#pragma unroll
        for (int n = 0; n < 4; n++) {
            int col = n0 + wn * 32 + n * 8 + qc;
            float b0 = fcb[col], b1 = fcb[col + 1];
            int row = m0 + wm * 32 + f * 16 + qr;
            __half2 v0, v1;
            v0.x = __float2half_rn(fmaxf(acc[f][n][0] + b0, 0.f));
            v0.y = __float2half_rn(fmaxf(acc[f][n][1] + b1, 0.f));
            v1.x = __float2half_rn(fmaxf(acc[f][n][2] + b0, 0.f));
            v1.y = __float2half_rn(fmaxf(acc[f][n][3] + b1, 0.f));
            *reinterpret_cast<__half2*>(&g_hh[(size_t)row * KH + col]) = v0;
            *reinterpret_cast<__half2*>(&g_hh[(size_t)(row + 8) * KH + col]) = v1;
        }
    }
}

// ============ K6: phase2 via tensor cores ============
#define P2_STG 56320
#define P2_BOFF 11264
#define P2SMEM (2 * P2_STG)

__global__ void __launch_bounds__(256) phase2_kernel(const float* __restrict__ b1,
                                                     const float* __restrict__ W2,
                                                     const float* __restrict__ b2,
                                                     float* __restrict__ out) {
    extern __shared__ char smem[];
    const uint32_t sb = smem_u32(smem);
    __shared__ int ridx[64];
    const int hd = blockIdx.y;
    const int cnt = g_cnt[hd], base = g_off[hd];
    const int r0 = blockIdx.x * 64;
    if (r0 >= cnt) return;
    const int tid = threadIdx.x;
    const int wid = tid >> 5, lane = tid & 31;
    const int wm = wid & 1, wn = wid >> 1;
    if (tid < 64) {
        int rr = r0 + tid;
        ridx[tid] = g_idx[base + (rr < cnt ? rr : 0)];
    }
    __syncthreads();

    const __half* W1h = g_W1t + (size_t)hd * U1 * KH;

#define P2_LOAD(stg, kb) do {                                                     \
    const int kb_ = (kb);                                                         \
    const uint32_t sa_ = sb + (stg) * P2_STG;                                     \
    _Pragma("unroll")                                                             \
    for (int j_ = 0; j_ < 3; j_++) {                                              \
        int q_ = tid + 256 * j_;                                                  \
        if (q_ < 640) {                                                           \
            int r_ = q_ / 10, c_ = q_ % 10;                                       \
            CP_ASYNC16(sa_ + r_ * 176 + c_ * 16,                                  \
                       g_hh + (size_t)ridx[r_] * KH + kb_ + c_ * 8);              \
        }                                                                         \
    }                                                                             \
    _Pragma("unroll")                                                             \
    for (int j_ = 0; j_ < 10; j_++) {                                             \
        int q_ = tid + 256 * j_;                                                  \
        int r_ = q_ / 10, c_ = q_ % 10;                                           \
        CP_ASYNC16(sa_ + P2_BOFF + r_ * 176 + c_ * 16,                            \
                   W1h + (size_t)r_ * KH + kb_ + c_ * 8);                         \
    }                                                                             \
} while (0)

    float acc[2][8][4];
#pragma unroll
    for (int f = 0; f < 2; f++)
#pragma unroll
        for (int n = 0; n < 8; n++)
#pragma unroll
            for (int j = 0; j < 4; j++) acc[f][n][j] = 0.f;

    const int trow = (lane & 7) + ((lane >> 3) & 1) * 8;
    const int tkc = lane >> 4;

    P2_LOAD(0, 0);
    CP_COMMIT();

    for (int c = 0; c < 13; c++) {
        if (c + 1 < 13) P2_LOAD((c + 1) & 1, (c + 1) * 80);
        CP_COMMIT();
        CP_WAIT1();
        __syncthreads();
        const uint32_t sa = sb + (c & 1) * P2_STG;
#pragma unroll
        for (int kk = 0; kk < 5; kk++) {
            const int kc = kk * 2 + tkc;
            uint32_t ah[2][4];
            uint32_t bf[8][2];
#pragma unroll
            for (int f = 0; f < 2; f++) {
                int row = wm * 32 + f * 16 + trow;
                LDMX4(ah[f][0], ah[f][1], ah[f][2], ah[f][3], sa + row * 176 + kc * 16);
            }
#pragma unroll
            for (int p = 0; p < 4; p++) {
                int row = wn * 64 + p * 16 + trow;
                uint32_t r0_, r1_, r2_, r3_;
                LDMX4(r0_, r1_, r2_, r3_, sa + P2_BOFF + row * 176 + kc * 16);
                bf[2 * p][0] = r0_; bf[2 * p][1] = r2_;
                bf[2 * p + 1][0] = r1_; bf[2 * p + 1][1] = r3_;
            }
#pragma unroll
            for (int f = 0; f < 2; f++)
#pragma unroll
                for (int n = 0; n < 8; n++)
                    MMA16816(acc[f][n], ah[f], bf[n][0], bf[n][1]);
        }
        __syncthreads();
    }

    // h1 = relu(acc + b1) -> smem fp32 [64][264]
    float* buf = reinterpret_cast<float*>(smem);
    const int qr = lane >> 2, qc = (lane & 3) << 1;
    __syncthreads();
#pragma unroll
    for (int f = 0; f < 2; f++) {
#pragma unroll
        for (int n = 0; n < 8; n++) {
            int col = wn * 64 + n * 8 + qc;
            float bb0 = b1[hd * 256 + col], bb1 = b1[hd * 256 + col + 1];
            int row = wm * 32 + f * 16 + qr;
            buf[row * 264 + col] = fmaxf(acc[f][n][0] + bb0, 0.f);
            buf[row * 264 + col + 1] = fmaxf(acc[f][n][1] + bb1, 0.f);
            buf[(row + 8) * 264 + col] = fmaxf(acc[f][n][2] + bb0, 0.f);
            buf[(row + 8) * 264 + col + 1] = fmaxf(acc[f][n][3] + bb1, 0.f);
        }
    }
    __syncthreads();

    // h2 = h1 @ W2 + b2, epilogue
    {
        int row = tid >> 2, o = tid & 3;
        const float* W2h = W2 + hd * 256 * 4;
        float a = b2[hd * 4 + o];
#pragma unroll 8
        for (int k = 0; k < 256; k++) a += buf[row * 264 + k] * W2h[k * 4 + o];
        int rr = r0 + row;
        if (rr < cnt) {
            int bi = ridx[row];
            float v;
            if (o < 2) {
                v = 5.f * tanhf(a * 0.2f);
            } else {
                float t = a + 4.9932394f;
                v = ((t > 20.f) ? t : log1pf(expf(t))) + 1e-4f;
            }
            out[bi * 4 + o] = v;
        }
    }
}

extern "C" void kernel_launch(void* const* d_in, const int* in_sizes, int n_in,
                              void* d_out, int out_size) {
    const float* x   = (const float*)d_in[0];
    const int* cmd   = (const int*)d_in[1];
    const float* ego = (const float*)d_in[2];
    const float* fcW = (const float*)d_in[3];
    const float* fcb = (const float*)d_in[4];
    const float* W1  = (const float*)d_in[5];
    const float* b1  = (const float*)d_in[6];
    const float* W2  = (const float*)d_in[7];
    const float* b2  = (const float*)d_in[8];
    float* out = (float*)d_out;

    static int smem_set = 0;
    if (!smem_set) {
        cudaFuncSetAttribute(gemm1_kernel, cudaFuncAttributeMaxDynamicSharedMemorySize,
                             NSTAGE * STG_BYTES);
        cudaFuncSetAttribute(phase2_kernel, cudaFuncAttributeMaxDynamicSharedMemorySize,
                             P2SMEM);
        smem_set = 1;
    }

    convert_w_kernel<<<dim3(32, 256), dim3(32, 8)>>>(fcW);
    convert_w1_kernel<<<dim3(33, 8, NHEAD), dim3(32, 8)>>>(W1);
    ego_kernel<<<(BATCH * 16) / 256, 256>>>(ego);
    prep_kernel<<<1, 1024>>>(cmd);
    gemm1_kernel<<<dim3(8, 64), 512, NSTAGE * STG_BYTES>>>(x, fcb);
    phase2_kernel<<<dim3(BATCH / 64, NHEAD), 256, P2SMEM>>>(b1, W2, b2, out);
}

// round 14
// speedup vs baseline: 1.1657x; 1.1657x over previous
#include <cuda_runtime.h>
#include <cuda_fp16.h>
#include <cstdint>

#define EMBED 8192
#define U0 1024
#define KH 1040
#define U1 256
#define NHEAD 6
#define BATCH 8192

__device__ __align__(16) __half g_Wt[(size_t)U0 * EMBED];
__device__ __align__(16) __half g_hh[(size_t)BATCH * KH];
__device__ __align__(16) __half g_W1t[(size_t)NHEAD * U1 * KH];
__device__ int g_idx[BATCH];
__device__ int g_cnt[NHEAD];
__device__ int g_off[NHEAD];

__device__ __forceinline__ uint32_t smem_u32(const void* p) {
    uint32_t a;
    asm("{ .reg .u64 t; cvta.to.shared.u64 t, %1; cvt.u32.u64 %0, t; }" : "=r"(a) : "l"(p));
    return a;
}
__device__ __forceinline__ uint32_t packh2(float a, float b) {
    __half2 h = __floats2half2_rn(a, b);
    return *reinterpret_cast<uint32_t*>(&h);
}

#define CP_ASYNC16(dst, src) \
    asm volatile("cp.async.cg.shared.global [%0], [%1], 16;" ::"r"(dst), "l"(src))
#define CP_COMMIT() asm volatile("cp.async.commit_group;" ::: "memory")
#define CP_WAIT3()  asm volatile("cp.async.wait_group 3;" ::: "memory")
#define CP_WAIT2()  asm volatile("cp.async.wait_group 2;" ::: "memory")
#define CP_WAIT1()  asm volatile("cp.async.wait_group 1;" ::: "memory")

#define LDMX4(r0, r1, r2, r3, a) \
    asm volatile("ldmatrix.sync.aligned.m8n8.x4.shared.b16 {%0,%1,%2,%3}, [%4];" \
        : "=r"(r0), "=r"(r1), "=r"(r2), "=r"(r3) : "r"(a))

#define STS128(addr, r0, r1, r2, r3) \
    asm volatile("st.shared.v4.b32 [%0], {%1,%2,%3,%4};" ::"r"(addr), "r"(r0), "r"(r1), "r"(r2), "r"(r3) : "memory")

#define MMA16816(c, a, b0, b1)                                                   \
    asm volatile("mma.sync.aligned.m16n8k16.row.col.f32.f16.f16.f32 "            \
        "{%0,%1,%2,%3}, {%4,%5,%6,%7}, {%8,%9}, {%0,%1,%2,%3};"                  \
        : "+f"((c)[0]), "+f"((c)[1]), "+f"((c)[2]), "+f"((c)[3])                 \
        : "r"((a)[0]), "r"((a)[1]), "r"((a)[2]), "r"((a)[3]), "r"(b0), "r"(b1))

// ============ K2: transpose fc_W [K][N] fp32 -> g_Wt [N][K] fp16 ============
__global__ void convert_w_kernel(const float* __restrict__ W) {
    __shared__ float tile[32][33];
    const int bx = blockIdx.x, by = blockIdx.y;
    const int tx = threadIdx.x, ty = threadIdx.y;
#pragma unroll
    for (int r = 0; r < 4; r++)
        tile[ty + r * 8][tx] = W[(size_t)(by * 32 + ty + r * 8) * U0 + bx * 32 + tx];
    __syncthreads();
#pragma unroll
    for (int r = 0; r < 4; r++) {
        int n = bx * 32 + ty + r * 8, k = by * 32 + tx;
        g_Wt[(size_t)n * EMBED + k] = __float2half_rn(tile[tx][ty + r * 8]);
    }
}

// ============ K2b: W1 [h][k(1027)][n(256)] -> g_W1t [h][n][k(1040 pad)] fp16 ============
__global__ void convert_w1_kernel(const float* __restrict__ W1) {
    __shared__ float tile[32][33];
    const int kt = blockIdx.x, nt = blockIdx.y, hd = blockIdx.z;
    const int tx = threadIdx.x, ty = threadIdx.y;
    const float* Wh = W1 + (size_t)hd * 1027 * 256;
#pragma unroll
    for (int r = 0; r < 4; r++) {
        int k = kt * 32 + ty + r * 8, n = nt * 32 + tx;
        tile[ty + r * 8][tx] = (k < 1027) ? Wh[(size_t)k * 256 + n] : 0.f;
    }
    __syncthreads();
#pragma unroll
    for (int r = 0; r < 4; r++) {
        int n = nt * 32 + ty + r * 8, k = kt * 32 + tx;
        if (k < KH)
            g_W1t[(size_t)hd * U1 * KH + (size_t)n * KH + k] = __float2half_rn(tile[tx][ty + r * 8]);
    }
}

// ============ K3: ego columns + zero pad of g_hh cols [1024,1040) fp16 ============
__global__ void ego_kernel(const float* __restrict__ ego) {
    int i = blockIdx.x * 256 + threadIdx.x;
    if (i >= BATCH * 16) return;
    int b = i >> 4, j = i & 15;
    g_hh[(size_t)b * KH + U0 + j] = __float2half_rn((j < 3) ? ego[b * 3 + j] : 0.f);
}

// ============ K4: bin rows by command (1 block, 1024 thr) ============
__global__ void prep_kernel(const int* __restrict__ cmd) {
    __shared__ int scnt[NHEAD], scur[NHEAD];
    const int tid = threadIdx.x;
    if (tid < NHEAD) scnt[tid] = 0;
    __syncthreads();
    for (int b = tid; b < BATCH; b += 1024) {
        int c = cmd[b];
        unsigned m = __match_any_sync(0xFFFFFFFFu, c);
        if ((tid & 31) == __ffs(m) - 1) atomicAdd(&scnt[c], __popc(m));
    }
    __syncthreads();
    if (tid == 0) {
        int run = 0;
        for (int g = 0; g < NHEAD; g++) { g_off[g] = run; g_cnt[g] = scnt[g]; scur[g] = run; run += scnt[g]; }
    }
    __syncthreads();
    for (int b = tid; b < BATCH; b += 1024) {
        int c = cmd[b];
        unsigned m = __match_any_sync(0xFFFFFFFFu, c);
        int leader = __ffs(m) - 1, base = 0;
        if ((tid & 31) == leader) base = atomicAdd(&scur[c], __popc(m));
        base = __shfl_sync(m, base, leader);
        g_idx[base + __popc(m & ((1u << (tid & 31)) - 1u))] = b;
    }
}

// ============ K5: GEMM1 h = relu(x @ fc_W + b) -> g_hh fp16 ============
// A: cp.async fp32 into A32[5 stages], converted smem->smem one stage ahead
// into A16[2]. W: cp.async fp16 W16[5]. 512 threads, warp tile m32 x n32.
#define A32_STG 16384
#define A16_OFF 81920
#define W_OFF 98304
#define GSMEM 139264
#define NITER 256

__global__ void __launch_bounds__(512) gemm1_kernel(const float* __restrict__ x,
                                                    const float* __restrict__ fcb) {
    extern __shared__ char smem[];
    const uint32_t sb = smem_u32(smem);
    const int tid = threadIdx.x;
    const int wid = tid >> 5, lane = tid & 31;
    const int wm = wid & 3, wn = wid >> 2;
    const int m0 = blockIdx.y * 128, n0 = blockIdx.x * 128;

    const __half* wt = g_Wt + (size_t)n0 * EMBED;

    const int lr = tid >> 2, lc = tid & 3;
    const uint32_t lsw0 = (uint32_t)(lr * 64 + ((lc ^ ((lr >> 1) & 3)) << 4));
    // A32 load mapping: q in [0,1024): row=q>>3, chunk c=q&7 (16B = 4 fp32)
    const int ar0 = tid >> 3, ac0 = tid & 7;
    const int ar1 = (tid + 512) >> 3, ac1 = (tid + 512) & 7;

#define G1_LOAD(stg, k0) do {                                                     \
    const int k0_ = (k0);                                                         \
    const uint32_t as_ = sb + (stg) * A32_STG;                                    \
    CP_ASYNC16(as_ + ar0 * 128 + ac0 * 16, x + (size_t)(m0 + ar0) * EMBED + k0_ + ac0 * 4); \
    CP_ASYNC16(as_ + ar1 * 128 + ac1 * 16, x + (size_t)(m0 + ar1) * EMBED + k0_ + ac1 * 4); \
    CP_ASYNC16(sb + W_OFF + (stg) * 8192 + lsw0, wt + (size_t)lr * EMBED + k0_ + lc * 8);   \
} while (0)

#define G1_CONV(stg, buf) do {                                                    \
    const float4* pa_ = reinterpret_cast<const float4*>(smem + (stg) * A32_STG + lr * 128 + lc * 32); \
    float4 f0_ = pa_[0], f1_ = pa_[1];                                            \
    uint32_t p0_ = packh2(f0_.x, f0_.y), p1_ = packh2(f0_.z, f0_.w);              \
    uint32_t p2_ = packh2(f1_.x, f1_.y), p3_ = packh2(f1_.z, f1_.w);              \
    STS128(sb + A16_OFF + (buf) * 8192 + lsw0, p0_, p1_, p2_, p3_);               \
} while (0)

    // prologue: stages 0..3
#pragma unroll
    for (int s = 0; s < 4; s++) { G1_LOAD(s, s * 32); CP_COMMIT(); }
    CP_WAIT3();
    __syncthreads();
    G1_CONV(0, 0);  // stage 0 -> A16 buf 0 (visible after iter-0 sync)

    float acc[2][4][4];
#pragma unroll
    for (int f = 0; f < 2; f++)
#pragma unroll
        for (int n = 0; n < 4; n++)
#pragma unroll
            for (int j = 0; j < 4; j++) acc[f][n][j] = 0.f;

    const int trow = (lane & 7) + ((lane >> 3) & 1) * 8;
    const int tkc = lane >> 4;

    int stc = 0, stl = 4;  // compute stage (i%5), load stage ((i+4)%5)
    for (int it = 0; it < NITER; it++) {
        CP_WAIT2();          // stage it+1 landed
        __syncthreads();
        if (it + 4 < NITER) G1_LOAD(stl, (it + 4) * 32);
        CP_COMMIT();
        if (it + 1 < NITER) {
            int stv = (stc == 4) ? 0 : stc + 1;
            G1_CONV(stv, (it + 1) & 1);
        }

        const uint32_t sA = sb + A16_OFF + (it & 1) * 8192;
        const uint32_t sW = sb + W_OFF + stc * 8192;
#pragma unroll
        for (int ks = 0; ks < 2; ks++) {
            uint32_t ah[2][4];
            uint32_t bf[4][2];
            const int kc = ks * 2 + tkc;
#pragma unroll
            for (int f = 0; f < 2; f++) {
                int row = wm * 32 + f * 16 + trow;
                uint32_t ad = sA + row * 64 + ((kc ^ ((row >> 1) & 3)) << 4);
                LDMX4(ah[f][0], ah[f][1], ah[f][2], ah[f][3], ad);
            }
#pragma unroll
            for (int p = 0; p < 2; p++) {
                int row = wn * 32 + p * 16 + trow;
                uint32_t bd = sW + row * 64 + ((kc ^ ((row >> 1) & 3)) << 4);
                uint32_t r0, r1, r2, r3;
                LDMX4(r0, r1, r2, r3, bd);
                bf[2 * p][0] = r0; bf[2 * p][1] = r2;
                bf[2 * p + 1][0] = r1; bf[2 * p + 1][1] = r3;
            }
#pragma unroll
            for (int f = 0; f < 2; f++)
#pragma unroll
                for (int n = 0; n < 4; n++)
                    MMA16816(acc[f][n], ah[f], bf[n][0], bf[n][1]);
        }
        stc = (stc == 4) ? 0 : stc + 1;
        stl = (stl == 4) ? 0 : stl + 1;
    }

    const int qr = lane >> 2, qc = (lane & 3) << 1;
#pragma unroll
    for (int f = 0; f < 2; f++) {
#pragma unroll
        for (int n = 0; n < 4; n++) {
            int col = n0 + wn * 32 + n * 8 + qc;
            float b0 = fcb[col], b1 = fcb[col + 1];
            int row = m0 + wm * 32 + f * 16 + qr;
            __half2 v0, v1;
            v0.x = __float2half_rn(fmaxf(acc[f][n][0] + b0, 0.f));
            v0.y = __float2half_rn(fmaxf(acc[f][n][1] + b1, 0.f));
            v1.x = __float2half_rn(fmaxf(acc[f][n][2] + b0, 0.f));
            v1.y = __float2half_rn(fmaxf(acc[f][n][3] + b1, 0.f));
            *reinterpret_cast<__half2*>(&g_hh[(size_t)row * KH + col]) = v0;
            *reinterpret_cast<__half2*>(&g_hh[(size_t)(row + 8) * KH + col]) = v1;
        }
    }
}

// ============ K6: phase2 via tensor cores (proven R12 version) ============
#define P2_STG 56320
#define P2_BOFF 11264
#define P2SMEM (2 * P2_STG)

__global__ void __launch_bounds__(256) phase2_kernel(const float* __restrict__ b1,
                                                     const float* __restrict__ W2,
                                                     const float* __restrict__ b2,
                                                     float* __restrict__ out) {
    extern __shared__ char smem[];
    const uint32_t sb = smem_u32(smem);
    __shared__ int ridx[64];
    const int hd = blockIdx.y;
    const int cnt = g_cnt[hd], base = g_off[hd];
    const int r0 = blockIdx.x * 64;
    if (r0 >= cnt) return;
    const int tid = threadIdx.x;
    const int wid = tid >> 5, lane = tid & 31;
    const int wm = wid & 1, wn = wid >> 1;
    if (tid < 64) {
        int rr = r0 + tid;
        ridx[tid] = g_idx[base + (rr < cnt ? rr : 0)];
    }
    __syncthreads();

    const __half* W1h = g_W1t + (size_t)hd * U1 * KH;

#define P2_LOAD(stg, kb) do {                                                     \
    const int kb_ = (kb);                                                         \
    const uint32_t sa_ = sb + (stg) * P2_STG;                                     \
    _Pragma("unroll")                                                             \
    for (int j_ = 0; j_ < 3; j_++) {                                              \
        int q_ = tid + 256 * j_;                                                  \
        if (q_ < 640) {                                                           \
            int r_ = q_ / 10, c_ = q_ % 10;                                       \
            CP_ASYNC16(sa_ + r_ * 176 + c_ * 16,                                  \
                       g_hh + (size_t)ridx[r_] * KH + kb_ + c_ * 8);              \
        }                                                                         \
    }                                                                             \
    _Pragma("unroll")                                                             \
    for (int j_ = 0; j_ < 10; j_++) {                                             \
        int q_ = tid + 256 * j_;                                                  \
        int r_ = q_ / 10, c_ = q_ % 10;                                           \
        CP_ASYNC16(sa_ + P2_BOFF + r_ * 176 + c_ * 16,                            \
                   W1h + (size_t)r_ * KH + kb_ + c_ * 8);                         \
    }                                                                             \
} while (0)

    float acc[2][8][4];
#pragma unroll
    for (int f = 0; f < 2; f++)
#pragma unroll
        for (int n = 0; n < 8; n++)
#pragma unroll
            for (int j = 0; j < 4; j++) acc[f][n][j] = 0.f;

    const int trow = (lane & 7) + ((lane >> 3) & 1) * 8;
    const int tkc = lane >> 4;

    P2_LOAD(0, 0);
    CP_COMMIT();

    for (int c = 0; c < 13; c++) {
        if (c + 1 < 13) P2_LOAD((c + 1) & 1, (c + 1) * 80);
        CP_COMMIT();
        CP_WAIT1();
        __syncthreads();
        const uint32_t sa = sb + (c & 1) * P2_STG;
#pragma unroll
        for (int kk = 0; kk < 5; kk++) {
            const int kc = kk * 2 + tkc;
            uint32_t ah[2][4];
            uint32_t bf[8][2];
#pragma unroll
            for (int f = 0; f < 2; f++) {
                int row = wm * 32 + f * 16 + trow;
                LDMX4(ah[f][0], ah[f][1], ah[f][2], ah[f][3], sa + row * 176 + kc * 16);
            }
#pragma unroll
            for (int p = 0; p < 4; p++) {
                int row = wn * 64 + p * 16 + trow;
                uint32_t r0_, r1_, r2_, r3_;
                LDMX4(r0_, r1_, r2_, r3_, sa + P2_BOFF + row * 176 + kc * 16);
                bf[2 * p][0] = r0_; bf[2 * p][1] = r2_;
                bf[2 * p + 1][0] = r1_; bf[2 * p + 1][1] = r3_;
            }
#pragma unroll
            for (int f = 0; f < 2; f++)
#pragma unroll
                for (int n = 0; n < 8; n++)
                    MMA16816(acc[f][n], ah[f], bf[n][0], bf[n][1]);
        }
        __syncthreads();
    }

    float* buf = reinterpret_cast<float*>(smem);
    const int qr = lane >> 2, qc = (lane & 3) << 1;
    __syncthreads();
#pragma unroll
    for (int f = 0; f < 2; f++) {
#pragma unroll
        for (int n = 0; n < 8; n++) {
            int col = wn * 64 + n * 8 + qc;
            float bb0 = b1[hd * 256 + col], bb1 = b1[hd * 256 + col + 1];
            int row = wm * 32 + f * 16 + qr;
            buf[row * 264 + col] = fmaxf(acc[f][n][0] + bb0, 0.f);
            buf[row * 264 + col + 1] = fmaxf(acc[f][n][1] + bb1, 0.f);
            buf[(row + 8) * 264 + col] = fmaxf(acc[f][n][2] + bb0, 0.f);
            buf[(row + 8) * 264 + col + 1] = fmaxf(acc[f][n][3] + bb1, 0.f);
        }
    }
    __syncthreads();

    {
        int row = tid >> 2, o = tid & 3;
        const float* W2h = W2 + hd * 256 * 4;
        float a = b2[hd * 4 + o];
#pragma unroll 8
        for (int k = 0; k < 256; k++) a += buf[row * 264 + k] * W2h[k * 4 + o];
        int rr = r0 + row;
        if (rr < cnt) {
            int bi = ridx[row];
            float v;
            if (o < 2) {
                v = 5.f * tanhf(a * 0.2f);
            } else {
                float t = a + 4.9932394f;
                v = ((t > 20.f) ? t : log1pf(expf(t))) + 1e-4f;
            }
            out[bi * 4 + o] = v;
        }
    }
}

extern "C" void kernel_launch(void* const* d_in, const int* in_sizes, int n_in,
                              void* d_out, int out_size) {
    const float* x   = (const float*)d_in[0];
    const int* cmd   = (const int*)d_in[1];
    const float* ego = (const float*)d_in[2];
    const float* fcW = (const float*)d_in[3];
    const float* fcb = (const float*)d_in[4];
    const float* W1  = (const float*)d_in[5];
    const float* b1  = (const float*)d_in[6];
    const float* W2  = (const float*)d_in[7];
    const float* b2  = (const float*)d_in[8];
    float* out = (float*)d_out;

    static int smem_set = 0;
    if (!smem_set) {
        cudaFuncSetAttribute(gemm1_kernel, cudaFuncAttributeMaxDynamicSharedMemorySize, GSMEM);
        cudaFuncSetAttribute(phase2_kernel, cudaFuncAttributeMaxDynamicSharedMemorySize, P2SMEM);
        smem_set = 1;
    }

    convert_w_kernel<<<dim3(32, 256), dim3(32, 8)>>>(fcW);
    convert_w1_kernel<<<dim3(33, 8, NHEAD), dim3(32, 8)>>>(W1);
    ego_kernel<<<(BATCH * 16) / 256, 256>>>(ego);
    prep_kernel<<<1, 1024>>>(cmd);
    gemm1_kernel<<<dim3(8, 64), 512, GSMEM>>>(x, fcb);
    phase2_kernel<<<dim3(BATCH / 64, NHEAD), 256, P2SMEM>>>(b1, W2, b2, out);
}

// round 17
// speedup vs baseline: 1.4326x; 1.2289x over previous
#include <cuda_runtime.h>
#include <cuda_fp16.h>
#include <cstdint>

#define EMBED 8192
#define U0 1024
#define KH 1040
#define U1 256
#define NHEAD 6
#define BATCH 8192

__device__ __align__(16) __half g_xh[(size_t)BATCH * EMBED];
__device__ __align__(16) __half g_Wt[(size_t)U0 * EMBED];
__device__ __align__(16) __half g_hh[(size_t)BATCH * KH];
__device__ __align__(16) __half g_W1t[(size_t)NHEAD * U1 * KH];
__device__ int g_idx[BATCH];
__device__ int g_cnt[NHEAD];
__device__ int g_off[NHEAD];

__device__ __forceinline__ uint32_t smem_u32(const void* p) {
    uint32_t a;
    asm("{ .reg .u64 t; cvta.to.shared.u64 t, %1; cvt.u32.u64 %0, t; }" : "=r"(a) : "l"(p));
    return a;
}
__device__ __forceinline__ uint32_t packh2(float a, float b) {
    __half2 h = __floats2half2_rn(a, b);
    return *reinterpret_cast<uint32_t*>(&h);
}

#define CP_ASYNC16(dst, src) \
    asm volatile("cp.async.cg.shared.global [%0], [%1], 16;" ::"r"(dst), "l"(src))
#define CP_COMMIT() asm volatile("cp.async.commit_group;" ::: "memory")
#define CP_WAIT2()  asm volatile("cp.async.wait_group 2;" ::: "memory")
#define CP_WAIT1()  asm volatile("cp.async.wait_group 1;" ::: "memory")

#define LDMX4(r0, r1, r2, r3, a) \
    asm volatile("ldmatrix.sync.aligned.m8n8.x4.shared.b16 {%0,%1,%2,%3}, [%4];" \
        : "=r"(r0), "=r"(r1), "=r"(r2), "=r"(r3) : "r"(a))

#define MMA16816(c, a, b0, b1)                                                   \
    asm volatile("mma.sync.aligned.m16n8k16.row.col.f32.f16.f16.f32 "            \
        "{%0,%1,%2,%3}, {%4,%5,%6,%7}, {%8,%9}, {%0,%1,%2,%3};"                  \
        : "+f"((c)[0]), "+f"((c)[1]), "+f"((c)[2]), "+f"((c)[3])                 \
        : "r"((a)[0]), "r"((a)[1]), "r"((a)[2]), "r"((a)[3]), "r"(b0), "r"(b1))

// ============ K1: x -> fp16 (64B per thread) ============
__global__ void convert_x_kernel(const float* __restrict__ x) {
    size_t i = ((size_t)blockIdx.x * 512 + threadIdx.x) * 4;  // 4 float4s
    const float4* src = reinterpret_cast<const float4*>(x);
    float4 v0 = src[i], v1 = src[i + 1], v2 = src[i + 2], v3 = src[i + 3];
    uint4 pa, pb;
    pa.x = packh2(v0.x, v0.y); pa.y = packh2(v0.z, v0.w);
    pa.z = packh2(v1.x, v1.y); pa.w = packh2(v1.z, v1.w);
    pb.x = packh2(v2.x, v2.y); pb.y = packh2(v2.z, v2.w);
    pb.z = packh2(v3.x, v3.y); pb.w = packh2(v3.z, v3.w);
    uint4* dst = reinterpret_cast<uint4*>(g_xh);
    dst[i >> 1] = pa;
    dst[(i >> 1) + 1] = pb;
}

// ============ K2: transpose fc_W [K][N] fp32 -> g_Wt [N][K] fp16 ============
__global__ void convert_w_kernel(const float* __restrict__ W) {
    __shared__ float tile[32][33];
    const int bx = blockIdx.x, by = blockIdx.y;
    const int tx = threadIdx.x, ty = threadIdx.y;
#pragma unroll
    for (int r = 0; r < 4; r++)
        tile[ty + r * 8][tx] = W[(size_t)(by * 32 + ty + r * 8) * U0 + bx * 32 + tx];
    __syncthreads();
#pragma unroll
    for (int r = 0; r < 4; r++) {
        int n = bx * 32 + ty + r * 8, k = by * 32 + tx;
        g_Wt[(size_t)n * EMBED + k] = __float2half_rn(tile[tx][ty + r * 8]);
    }
}

// ============ K2b: W1 [h][k(1027)][n(256)] -> g_W1t [h][n][k(1040 pad)] fp16 ============
__global__ void convert_w1_kernel(const float* __restrict__ W1) {
    __shared__ float tile[32][33];
    const int kt = blockIdx.x, nt = blockIdx.y, hd = blockIdx.z;
    const int tx = threadIdx.x, ty = threadIdx.y;
    const float* Wh = W1 + (size_t)hd * 1027 * 256;
#pragma unroll
    for (int r = 0; r < 4; r++) {
        int k = kt * 32 + ty + r * 8, n = nt * 32 + tx;
        tile[ty + r * 8][tx] = (k < 1027) ? Wh[(size_t)k * 256 + n] : 0.f;
    }
    __syncthreads();
#pragma unroll
    for (int r = 0; r < 4; r++) {
        int n = nt * 32 + ty + r * 8, k = kt * 32 + tx;
        if (k < KH)
            g_W1t[(size_t)hd * U1 * KH + (size_t)n * KH + k] = __float2half_rn(tile[tx][ty + r * 8]);
    }
}

// ============ K3: ego columns + zero pad of g_hh cols [1024,1040) fp16 ============
__global__ void ego_kernel(const float* __restrict__ ego) {
    int i = blockIdx.x * 256 + threadIdx.x;
    if (i >= BATCH * 16) return;
    int b = i >> 4, j = i & 15;
    g_hh[(size_t)b * KH + U0 + j] = __float2half_rn((j < 3) ? ego[b * 3 + j] : 0.f);
}

// ============ K4: bin rows by command (1 block, 1024 thr) ============
__global__ void prep_kernel(const int* __restrict__ cmd) {
    __shared__ int scnt[NHEAD], scur[NHEAD];
    const int tid = threadIdx.x;
    if (tid < NHEAD) scnt[tid] = 0;
    __syncthreads();
    for (int b = tid; b < BATCH; b += 1024) {
        int c = cmd[b];
        unsigned m = __match_any_sync(0xFFFFFFFFu, c);
        if ((tid & 31) == __ffs(m) - 1) atomicAdd(&scnt[c], __popc(m));
    }
    __syncthreads();
    if (tid == 0) {
        int run = 0;
        for (int g = 0; g < NHEAD; g++) { g_off[g] = run; g_cnt[g] = scnt[g]; scur[g] = run; run += scnt[g]; }
    }
    __syncthreads();
    for (int b = tid; b < BATCH; b += 1024) {
        int c = cmd[b];
        unsigned m = __match_any_sync(0xFFFFFFFFu, c);
        int leader = __ffs(m) - 1, base = 0;
        if ((tid & 31) == leader) base = atomicAdd(&scur[c], __popc(m));
        base = __shfl_sync(m, base, leader);
        g_idx[base + __popc(m & ((1u << (tid & 31)) - 1u))] = b;
    }
}

// ============ K5: GEMM1 h = relu(x @ fc_W + b) -> g_hh fp16, mma.sync ============
// BM=64 BN=128 BK=32 -> 1024 CTAs (6.92 waves on 148 SMs, ~1% tail).
// 512 threads, 16 warps as 2m x 8n (warp m32 x n16). 4-stage cp.async.
// Stage (12 KB): A 64x64B @+0, W 128x64B @+4096. Dynamic smem padded to
// 120 KB to force 1 CTA/SM.
#define STG_BYTES 12288
#define NSTAGE 4
#define NITER 256
#define GSMEM 122880

__global__ void __launch_bounds__(512) gemm1_kernel(const float* __restrict__ fcb) {
    extern __shared__ char smem[];
    const uint32_t sb = smem_u32(smem);
    const int tid = threadIdx.x;
    const int wid = tid >> 5, lane = tid & 31;
    const int wm = wid & 1, wn = wid >> 1;
    const int m0 = blockIdx.y * 64, n0 = blockIdx.x * 128;

    const __half* xh = g_xh + (size_t)m0 * EMBED;
    const __half* wt = g_Wt + (size_t)n0 * EMBED;

    // W tile: 128 rows x 4 chunks of 16B -> 512 threads, one chunk each
    const int lr = tid >> 2, lc = tid & 3;
    const uint32_t lsw0 = (uint32_t)(lr * 64 + ((lc ^ ((lr >> 1) & 3)) << 4));
    // A tile: 64 rows x 4 chunks -> threads [0,256)
    const int ar = tid >> 2;  // valid when tid < 256
    const uint32_t asw = (uint32_t)(ar * 64 + ((lc ^ ((ar >> 1) & 3)) << 4));

#define LOAD_STAGE(stg, k0) do {                                                  \
    uint32_t bsa = sb + (stg) * STG_BYTES;                                        \
    if (tid < 256)                                                                \
        CP_ASYNC16(bsa + asw, xh + (size_t)ar * EMBED + (k0) + lc * 8);           \
    CP_ASYNC16(bsa + 4096 + lsw0, wt + (size_t)lr * EMBED + (k0) + lc * 8);       \
} while (0)

    LOAD_STAGE(0, 0);  CP_COMMIT();
    LOAD_STAGE(1, 32); CP_COMMIT();
    LOAD_STAGE(2, 64); CP_COMMIT();

    float acc[2][2][4];
#pragma unroll
    for (int f = 0; f < 2; f++)
#pragma unroll
        for (int n = 0; n < 2; n++)
#pragma unroll
            for (int j = 0; j < 4; j++) acc[f][n][j] = 0.f;

    const int trow = (lane & 7) + ((lane >> 3) & 1) * 8;
    const int tkc = lane >> 4;

    for (int it = 0; it < NITER; it++) {
        CP_WAIT2();
        __syncthreads();
        if (it + 3 < NITER) LOAD_STAGE((it + 3) & 3, (it + 3) * 32);
        CP_COMMIT();

        const uint32_t sA = sb + (it & 3) * STG_BYTES;
#pragma unroll
        for (int ks = 0; ks < 2; ks++) {
            uint32_t ah[2][4];
            uint32_t bf[2][2];
            const int kc = ks * 2 + tkc;
#pragma unroll
            for (int f = 0; f < 2; f++) {
                int row = wm * 32 + f * 16 + trow;
                uint32_t ad = sA + row * 64 + ((kc ^ ((row >> 1) & 3)) << 4);
                LDMX4(ah[f][0], ah[f][1], ah[f][2], ah[f][3], ad);
            }
            {
                int row = wn * 16 + trow;
                uint32_t bd = sA + 4096 + row * 64 + ((kc ^ ((row >> 1) & 3)) << 4);
                uint32_t r0, r1, r2, r3;
                LDMX4(r0, r1, r2, r3, bd);
                bf[0][0] = r0; bf[0][1] = r2;
                bf[1][0] = r1; bf[1][1] = r3;
            }
#pragma unroll
            for (int f = 0; f < 2; f++)
#pragma unroll
                for (int n = 0; n < 2; n++)
                    MMA16816(acc[f][n], ah[f], bf[n][0], bf[n][1]);
        }
    }

    const int qr = lane >> 2, qc = (lane & 3) << 1;
#pragma unroll
    for (int f = 0; f < 2; f++) {
#pragma unroll
        for (int n = 0; n < 2; n++) {
            int col = n0 + wn * 16 + n * 8 + qc;
            float b0 = fcb[col], b1 = fcb[col + 1];
            int row = m0 + wm * 32 + f * 16 + qr;
            __half2 v0, v1;
            v0.x = __float2half_rn(fmaxf(acc[f][n][0] + b0, 0.f));
            v0.y = __float2half_rn(fmaxf(acc[f][n][1] + b1, 0.f));
            v1.x = __float2half_rn(fmaxf(acc[f][n][2] + b0, 0.f));
            v1.y = __float2half_rn(fmaxf(acc[f][n][3] + b1, 0.f));
            *reinterpret_cast<__half2*>(&g_hh[(size_t)row * KH + col]) = v0;
            *reinterpret_cast<__half2*>(&g_hh[(size_t)(row + 8) * KH + col]) = v1;
        }
    }
}

// ============ K6: phase2 via tensor cores (proven R12 version) ============
#define P2_STG 56320
#define P2_BOFF 11264
#define P2SMEM (2 * P2_STG)

__global__ void __launch_bounds__(256) phase2_kernel(const float* __restrict__ b1,
                                                     const float* __restrict__ W2,
                                                     const float* __restrict__ b2,
                                                     float* __restrict__ out) {
    extern __shared__ char smem[];
    const uint32_t sb = smem_u32(smem);
    __shared__ int ridx[64];
    const int hd = blockIdx.y;
    const int cnt = g_cnt[hd], base = g_off[hd];
    const int r0 = blockIdx.x * 64;
    if (r0 >= cnt) return;
    const int tid = threadIdx.x;
    const int wid = tid >> 5, lane = tid & 31;
    const int wm = wid & 1, wn = wid >> 1;
    if (tid < 64) {
        int rr = r0 + tid;
        ridx[tid] = g_idx[base + (rr < cnt ? rr : 0)];
    }
    __syncthreads();

    const __half* W1h = g_W1t + (size_t)hd * U1 * KH;

#define P2_LOAD(stg, kb) do {                                                     \
    const int kb_ = (kb);                                                         \
    const uint32_t sa_ = sb + (stg) * P2_STG;                                     \
    _Pragma("unroll")                                                             \
    for (int j_ = 0; j_ < 3; j_++) {                                              \
        int q_ = tid + 256 * j_;                                                  \
        if (q_ < 640) {                                                           \
            int r_ = q_ / 10, c_ = q_ % 10;                                       \
            CP_ASYNC16(sa_ + r_ * 176 + c_ * 16,                                  \
                       g_hh + (size_t)ridx[r_] * KH + kb_ + c_ * 8);              \
        }                                                                         \
    }                                                                             \
    _Pragma("unroll")                                                             \
    for (int j_ = 0; j_ < 10; j_++) {                                             \
        int q_ = tid + 256 * j_;                                                  \
        int r_ = q_ / 10, c_ = q_ % 10;                                           \
        CP_ASYNC16(sa_ + P2_BOFF + r_ * 176 + c_ * 16,                            \
                   W1h + (size_t)r_ * KH + kb_ + c_ * 8);                         \
    }                                                                             \
} while (0)

    float acc[2][8][4];
#pragma unroll
    for (int f = 0; f < 2; f++)
#pragma unroll
        for (int n = 0; n < 8; n++)
#pragma unroll
            for (int j = 0; j < 4; j++) acc[f][n][j] = 0.f;

    const int trow = (lane & 7) + ((lane >> 3) & 1) * 8;
    const int tkc = lane >> 4;

    P2_LOAD(0, 0);
    CP_COMMIT();

    for (int c = 0; c < 13; c++) {
        if (c + 1 < 13) P2_LOAD((c + 1) & 1, (c + 1) * 80);
        CP_COMMIT();
        CP_WAIT1();
        __syncthreads();
        const uint32_t sa = sb + (c & 1) * P2_STG;
#pragma unroll
        for (int kk = 0; kk < 5; kk++) {
            const int kc = kk * 2 + tkc;
            uint32_t ah[2][4];
            uint32_t bf[8][2];
#pragma unroll
            for (int f = 0; f < 2; f++) {
                int row = wm * 32 + f * 16 + trow;
                LDMX4(ah[f][0], ah[f][1], ah[f][2], ah[f][3], sa + row * 176 + kc * 16);
            }
#pragma unroll
            for (int p = 0; p < 4; p++) {
                int row = wn * 64 + p * 16 + trow;
                uint32_t r0_, r1_, r2_, r3_;
                LDMX4(r0_, r1_, r2_, r3_, sa + P2_BOFF + row * 176 + kc * 16);
                bf[2 * p][0] = r0_; bf[2 * p][1] = r2_;
                bf[2 * p + 1][0] = r1_; bf[2 * p + 1][1] = r3_;
            }
#pragma unroll
            for (int f = 0; f < 2; f++)
#pragma unroll
                for (int n = 0; n < 8; n++)
                    MMA16816(acc[f][n], ah[f], bf[n][0], bf[n][1]);
        }
        __syncthreads();
    }

    float* buf = reinterpret_cast<float*>(smem);
    const int qr = lane >> 2, qc = (lane & 3) << 1;
    __syncthreads();
#pragma unroll
    for (int f = 0; f < 2; f++) {
#pragma unroll
        for (int n = 0; n < 8; n++) {
            int col = wn * 64 + n * 8 + qc;
            float bb0 = b1[hd * 256 + col], bb1 = b1[hd * 256 + col + 1];
            int row = wm * 32 + f * 16 + qr;
            buf[row * 264 + col] = fmaxf(acc[f][n][0] + bb0, 0.f);
            buf[row * 264 + col + 1] = fmaxf(acc[f][n][1] + bb1, 0.f);
            buf[(row + 8) * 264 + col] = fmaxf(acc[f][n][2] + bb0, 0.f);
            buf[(row + 8) * 264 + col + 1] = fmaxf(acc[f][n][3] + bb1, 0.f);
        }
    }
    __syncthreads();

    {
        int row = tid >> 2, o = tid & 3;
        const float* W2h = W2 + hd * 256 * 4;
        float a = b2[hd * 4 + o];
#pragma unroll 8
        for (int k = 0; k < 256; k++) a += buf[row * 264 + k] * W2h[k * 4 + o];
        int rr = r0 + row;
        if (rr < cnt) {
            int bi = ridx[row];
            float v;
            if (o < 2) {
                v = 5.f * tanhf(a * 0.2f);
            } else {
                float t = a + 4.9932394f;
                v = ((t > 20.f) ? t : log1pf(expf(t))) + 1e-4f;
            }
            out[bi * 4 + o] = v;
        }
    }
}

extern "C" void kernel_launch(void* const* d_in, const int* in_sizes, int n_in,
                              void* d_out, int out_size) {
    const float* x   = (const float*)d_in[0];
    const int* cmd   = (const int*)d_in[1];
    const float* ego = (const float*)d_in[2];
    const float* fcW = (const float*)d_in[3];
    const float* fcb = (const float*)d_in[4];
    const float* W1  = (const float*)d_in[5];
    const float* b1  = (const float*)d_in[6];
    const float* W2  = (const float*)d_in[7];
    const float* b2  = (const float*)d_in[8];
    float* out = (float*)d_out;

    static int smem_set = 0;
    if (!smem_set) {
        cudaFuncSetAttribute(gemm1_kernel, cudaFuncAttributeMaxDynamicSharedMemorySize, GSMEM);
        cudaFuncSetAttribute(phase2_kernel, cudaFuncAttributeMaxDynamicSharedMemorySize, P2SMEM);
        smem_set = 1;
    }

    convert_x_kernel<<<(BATCH * EMBED / 16) / 512, 512>>>(x);
    convert_w_kernel<<<dim3(32, 256), dim3(32, 8)>>>(fcW);
    convert_w1_kernel<<<dim3(33, 8, NHEAD), dim3(32, 8)>>>(W1);
    ego_kernel<<<(BATCH * 16) / 256, 256>>>(ego);
    prep_kernel<<<1, 1024>>>(cmd);
    gemm1_kernel<<<dim3(8, 128), 512, GSMEM>>>(fcb);
    phase2_kernel<<<dim3(BATCH / 64, NHEAD), 256, P2SMEM>>>(b1, W2, b2, out);
}